// round 2
// baseline (speedup 1.0000x reference)
#include <cuda_runtime.h>
#include <math_constants.h>

#define BB 512
#define SS 200
#define UU 50
#define DD 32
#define NEG_INF_V (-1e9f)

__global__ __launch_bounds__(256, 6)
void DIB_attn_kernel(const float* __restrict__ cur_user,   // [B, D]
                     const float* __restrict__ sim_user,   // [B, S, U, D]
                     const float* __restrict__ cur_item,   // [B, S, D]
                     const int* __restrict__ mask,          // [B, S, U] (bool -> int32)
                     float* __restrict__ out)               // [B, S, D]
{
    const unsigned FULL = 0xffffffffu;
    int gwarp = (blockIdx.x * blockDim.x + threadIdx.x) >> 5;   // one warp per (b,s)
    int lane  = threadIdx.x & 31;
    if (gwarp >= BB * SS) return;

    int b = gwarp / SS;

    // lane owns dimension d = lane
    float cuv = __ldg(&cur_user[b * DD + lane]);

    const float* tile = sim_user + (long long)gwarp * (UU * DD);

    // Load the 50x32 tile (coalesced 128B rows) and compute 50 dot products.
    float v[UU];
    float sc0 = NEG_INF_V;      // score for u = lane          (lane < 32 <= U)
    float sc1 = -CUDART_INF_F;  // score for u = lane + 32     (valid iff lane+32 < U)

    #pragma unroll
    for (int u = 0; u < UU; u++) {
        v[u] = __ldg(&tile[u * DD + lane]);
        float p = cuv * v[u];
        #pragma unroll
        for (int o = 16; o > 0; o >>= 1)
            p += __shfl_xor_sync(FULL, p, o);
        // after butterfly every lane holds score[u]
        if (u < 32) { if (lane == u)        sc0 = p; }
        else        { if (lane == (u - 32)) sc1 = p; }
    }

    // Apply mask (True = masked out -> -1e9, matching reference NEG_INF).
    long long mbase = (long long)gwarp * UU;
    if (mask[mbase + lane] != 0) sc0 = NEG_INF_V;
    if (lane + 32 < UU) {
        if (mask[mbase + lane + 32] != 0) sc1 = NEG_INF_V;
    } // else sc1 stays -inf (padding -> weight 0)

    // Softmax over the 50 scores, distributed 2-per-lane.
    float mx = fmaxf(sc0, sc1);
    #pragma unroll
    for (int o = 16; o > 0; o >>= 1)
        mx = fmaxf(mx, __shfl_xor_sync(FULL, mx, o));

    float e0 = __expf(sc0 - mx);
    float e1 = (lane + 32 < UU) ? __expf(sc1 - mx) : 0.0f;

    float s = e0 + e1;
    #pragma unroll
    for (int o = 16; o > 0; o >>= 1)
        s += __shfl_xor_sync(FULL, s, o);

    float inv = __frcp_rn(s);
    float a0 = e0 * inv;   // attn[u = lane]
    float a1 = e1 * inv;   // attn[u = lane + 32]

    // Weighted sum over u: out[d] = sum_u attn[u] * v[u][d]
    float acc = 0.0f;
    #pragma unroll
    for (int u = 0; u < 32; u++)
        acc = fmaf(__shfl_sync(FULL, a0, u), v[u], acc);
    #pragma unroll
    for (int u = 32; u < UU; u++)
        acc = fmaf(__shfl_sync(FULL, a1, u - 32), v[u], acc);

    // Add current item embedding and write out.
    long long o_idx = (long long)gwarp * DD + lane;
    out[o_idx] = acc + __ldg(&cur_item[o_idx]);
}

extern "C" void kernel_launch(void* const* d_in, const int* in_sizes, int n_in,
                              void* d_out, int out_size) {
    // Select inputs by element count (robust to ordering):
    //   cur_user: 512*32        = 16384
    //   sim_user: 512*200*50*32 = 163840000
    //   cur_item: 512*200*32    = 3276800
    //   mask:     512*200*50    = 5120000
    const float* cur_user = nullptr;
    const float* sim_user = nullptr;
    const float* cur_item = nullptr;
    const int*   mask     = nullptr;
    for (int i = 0; i < n_in; i++) {
        switch (in_sizes[i]) {
            case 16384:     cur_user = (const float*)d_in[i]; break;
            case 163840000: sim_user = (const float*)d_in[i]; break;
            case 3276800:   cur_item = (const float*)d_in[i]; break;
            case 5120000:   mask     = (const int*)d_in[i];   break;
        }
    }
    float* out = (float*)d_out;

    int total_warps = BB * SS;              // 102400 (b,s) pairs, one warp each
    int threads = 256;                      // 8 warps / block
    int blocks = (total_warps * 32 + threads - 1) / threads;  // 12800
    DIB_attn_kernel<<<blocks, threads>>>(cur_user, sim_user, cur_item, mask, out);
}

// round 3
// speedup vs baseline: 1.7729x; 1.7729x over previous
#include <cuda_runtime.h>
#include <math_constants.h>

#define BB 512
#define SS 200
#define UU 50
#define DD 32
#define NITER 13          // ceil(50 rows / 4 rows-per-iter)
#define NEG_INF_V (-1e9f)

__global__ __launch_bounds__(256)
void DIB_attn_kernel(const float* __restrict__ cur_user,   // [B, D]
                     const float* __restrict__ sim_user,   // [B, S, U, D]
                     const float* __restrict__ cur_item,   // [B, S, D]
                     const int* __restrict__ mask,          // [B, S, U] (bool -> int32)
                     float* __restrict__ out)               // [B, S, D]
{
    const unsigned FULL = 0xffffffffu;
    int gwarp = (blockIdx.x * blockDim.x + threadIdx.x) >> 5;   // one warp per (b,s)
    if (gwarp >= BB * SS) return;
    int lane = threadIdx.x & 31;
    int sub  = lane >> 3;       // 0..3  : which row within a 4-row group
    int quad = lane & 7;        // 0..7  : dims quad*4 .. quad*4+3

    int b = gwarp / SS;

    // This lane's 4 dims of the current-user vector.
    float4 cu = __ldg((const float4*)(cur_user + b * DD) + quad);

    const float* tile = sim_user + (long long)gwarp * (UU * DD);
    const int*   mrow = mask     + (long long)gwarp * UU;

    // Pass over the 50x32 tile: one LDG.128 instruction covers 4 rows.
    // Row u = 4*i + sub is held (as float4 chunks) by the 8 lanes sharing `sub`.
    float4 v[NITER];
    float  sc[NITER];

    #pragma unroll
    for (int i = 0; i < NITER; i++) {
        int u = i * 4 + sub;
        bool valid = (u < UU);              // tail: i==12 has only rows 48,49
        float4 vv = make_float4(0.f, 0.f, 0.f, 0.f);
        if (valid) vv = __ldg((const float4*)(tile + u * DD) + quad);
        v[i] = vv;

        // partial dot over this lane's 4 dims, reduce across the 8 quads
        float p = vv.x * cu.x + vv.y * cu.y + vv.z * cu.z + vv.w * cu.w;
        p += __shfl_xor_sync(FULL, p, 1);
        p += __shfl_xor_sync(FULL, p, 2);
        p += __shfl_xor_sync(FULL, p, 4);   // all 8 lanes now hold score[u]

        int m = valid ? __ldg(mrow + u) : 1;
        sc[i] = valid ? (m ? NEG_INF_V : p) : -CUDART_INF_F;
    }

    // Softmax over 50 rows. Lane-local rows are {4i+sub}; union over sub = all.
    float mx = sc[0];
    #pragma unroll
    for (int i = 1; i < NITER; i++) mx = fmaxf(mx, sc[i]);
    mx = fmaxf(mx, __shfl_xor_sync(FULL, mx, 8));
    mx = fmaxf(mx, __shfl_xor_sync(FULL, mx, 16));

    float e[NITER];
    float s = 0.f;
    #pragma unroll
    for (int i = 0; i < NITER; i++) { e[i] = __expf(sc[i] - mx); s += e[i]; }
    s += __shfl_xor_sync(FULL, s, 8);
    s += __shfl_xor_sync(FULL, s, 16);
    float inv = __frcp_rn(s);

    // Weighted sum: attention weights are lane-local -> no shuffles in the MAC loop.
    float4 o = make_float4(0.f, 0.f, 0.f, 0.f);
    #pragma unroll
    for (int i = 0; i < NITER; i++) {
        float a = e[i] * inv;
        o.x = fmaf(a, v[i].x, o.x);
        o.y = fmaf(a, v[i].y, o.y);
        o.z = fmaf(a, v[i].z, o.z);
        o.w = fmaf(a, v[i].w, o.w);
    }

    // Reduce partial outputs across the 4 sub-groups (same dims, different rows).
    #pragma unroll
    for (int off = 8; off <= 16; off <<= 1) {
        o.x += __shfl_xor_sync(FULL, o.x, off);
        o.y += __shfl_xor_sync(FULL, o.y, off);
        o.z += __shfl_xor_sync(FULL, o.z, off);
        o.w += __shfl_xor_sync(FULL, o.w, off);
    }

    // sub==0 lanes (8 of them) write the 128B output row.
    if (sub == 0) {
        float4 ci = __ldg((const float4*)(cur_item + (long long)gwarp * DD) + quad);
        float4 r = make_float4(o.x + ci.x, o.y + ci.y, o.z + ci.z, o.w + ci.w);
        ((float4*)(out + (long long)gwarp * DD))[quad] = r;
    }
}

extern "C" void kernel_launch(void* const* d_in, const int* in_sizes, int n_in,
                              void* d_out, int out_size) {
    // Select inputs by element count (robust to ordering):
    const float* cur_user = nullptr;
    const float* sim_user = nullptr;
    const float* cur_item = nullptr;
    const int*   mask     = nullptr;
    for (int i = 0; i < n_in; i++) {
        switch (in_sizes[i]) {
            case 16384:     cur_user = (const float*)d_in[i]; break;
            case 163840000: sim_user = (const float*)d_in[i]; break;
            case 3276800:   cur_item = (const float*)d_in[i]; break;
            case 5120000:   mask     = (const int*)d_in[i];   break;
        }
    }
    float* out = (float*)d_out;

    int total_warps = BB * SS;              // 102400 (b,s) pairs, one warp each
    int threads = 256;                      // 8 warps / block
    int blocks = (total_warps * 32 + threads - 1) / threads;  // 12800
    DIB_attn_kernel<<<blocks, threads>>>(cur_user, sim_user, cur_item, mask, out);
}